// round 6
// baseline (speedup 1.0000x reference)
#include <cuda_runtime.h>
#include <cuda_bf16.h>
#include <cstdint>

// Problem shape (fixed)
#define Bb    4
#define T     1024
#define E     512
#define H     8
#define MTOT  (Bb*T)       // 4096
#define NPROJ (H*E)        // 4096
#define BH    (Bb*H)       // 32

#define NEG_INF (__int_as_float(0xff800000))
#define QK_SCALE 0.21022410381342864f   // 512^-0.25

typedef __nv_bfloat16 bf16;

// ---------------- scratch (device globals; no allocs allowed) ----------------
__device__ __align__(16) bf16 g_xh[MTOT * E],   g_xl[MTOT * E];
__device__ __align__(16) bf16 g_wkh[NPROJ * E], g_wkl[NPROJ * E];
__device__ __align__(16) bf16 g_wqh[NPROJ * E], g_wql[NPROJ * E];
__device__ __align__(16) bf16 g_wvh[NPROJ * E], g_wvl[NPROJ * E];
__device__ __align__(16) bf16 g_wuh[E * NPROJ], g_wul[E * NPROJ];
__device__ __align__(16) bf16 g_qh[MTOT * NPROJ], g_ql[MTOT * NPROJ];  // pre-scaled
__device__ __align__(16) bf16 g_kh[MTOT * NPROJ], g_kl[MTOT * NPROJ];  // pre-scaled
__device__ __align__(16) bf16 g_vth[(size_t)BH * E * T], g_vtl[(size_t)BH * E * T]; // (b,h,e,t)
__device__ float g_s[(size_t)BH * T * T];
__device__ __align__(16) bf16 g_ph[(size_t)BH * T * T], g_pl[(size_t)BH * T * T];
__device__ __align__(16) bf16 g_aoh[MTOT * NPROJ], g_aol[MTOT * NPROJ];

// ---------------------------------------------------------------------------
__device__ __forceinline__ uint32_t smem_u32(const void* p) {
    uint32_t a;
    asm("{ .reg .u64 t; cvta.to.shared.u64 t, %1; cvt.u32.u64 %0, t; }" : "=r"(a) : "l"(p));
    return a;
}
__device__ __forceinline__ void cp16(uint32_t dst, const void* src) {
    asm volatile("cp.async.cg.shared.global [%0], [%1], 16;" :: "r"(dst), "l"(src) : "memory");
}
#define CP_COMMIT()  asm volatile("cp.async.commit_group;" ::: "memory")
#define CP_WAIT(n)   asm volatile("cp.async.wait_group %0;" :: "n"(n) : "memory")

__device__ __forceinline__ void ldsm4(uint32_t* r, uint32_t addr) {
    asm volatile("ldmatrix.sync.aligned.m8n8.x4.shared.b16 {%0,%1,%2,%3}, [%4];"
                 : "=r"(r[0]), "=r"(r[1]), "=r"(r[2]), "=r"(r[3]) : "r"(addr));
}
__device__ __forceinline__ void mma16816(float* c, const uint32_t* a, const uint32_t* b) {
    asm volatile(
        "mma.sync.aligned.m16n8k16.row.col.f32.bf16.bf16.f32 "
        "{%0,%1,%2,%3}, {%4,%5,%6,%7}, {%8,%9}, {%0,%1,%2,%3};"
        : "+f"(c[0]), "+f"(c[1]), "+f"(c[2]), "+f"(c[3])
        : "r"(a[0]), "r"(a[1]), "r"(a[2]), "r"(a[3]), "r"(b[0]), "r"(b[1]));
}

__device__ __forceinline__ void f32split(float x, bf16& h, bf16& l) {
    h = __float2bfloat16(x);
    l = __float2bfloat16(x - __bfloat162float(h));
}

// all 5 arrays are exactly MTOT*E = 2M elements: one merged launch
__global__ void split_all(const float* __restrict__ x,  const float* __restrict__ wk,
                          const float* __restrict__ wq, const float* __restrict__ wv,
                          const float* __restrict__ wu) {
    const int i = blockIdx.x * 256 + threadIdx.x;
    const float* s; bf16 *h, *l;
    switch (blockIdx.y) {
        case 0:  s = x;  h = g_xh;  l = g_xl;  break;
        case 1:  s = wk; h = g_wkh; l = g_wkl; break;
        case 2:  s = wq; h = g_wqh; l = g_wql; break;
        case 3:  s = wv; h = g_wvh; l = g_wvl; break;
        default: s = wu; h = g_wuh; l = g_wul; break;
    }
    f32split(s[i], h[i], l[i]);
}

// swizzled byte offset for (row, 16B-group kg) in a [rows][32]bf16 tile (64B rows)
__device__ __forceinline__ uint32_t swz(int row, int kg) {
    return row * 64 + ((kg ^ ((row >> 1) & 3)) << 4);
}

// ---------------------------------------------------------------------------
// Templated GEMM core: C[BM,BN] = Ahi/lo[BM,K] x Bhi/lo[BN,K]^T (K-major, bf16x3)
// 256 threads, warp grid 4(m) x 2(n), warp tile WM=BM/4 x WN=BN/2.
// 3-stage cp.async pipeline, ONE __syncthreads per K-chunk (stage rotation
// guarantees the buffer loaded at iter i+1 was last read at iter i-1).
// ---------------------------------------------------------------------------
template<int BM, int BN>
__device__ __forceinline__ void tc_gemm(
    const bf16* __restrict__ Ah, const bf16* __restrict__ Al, int lda,
    const bf16* __restrict__ Bh, const bf16* __restrict__ Bl, int ldb,
    int K, float* acc)
{
    constexpr int WM = BM / 4, WN = BN / 2;
    constexpr int SA = BM * 64;          // bytes of one A array per stage
    constexpr int SB = BN * 64;
    constexpr int STG = 2 * SA + 2 * SB; // stage bytes
    extern __shared__ char sm[];

    const int tid  = threadIdx.x;
    const int lane = tid & 31;
    const int warp = tid >> 5;
    const int wm = warp >> 1, wn = warp & 1;

    // ldmatrix lane->element mapping
    const int arow = ((lane >> 3) & 1) * 8 + (lane & 7);
    const int akg  = (lane >> 4) & 1;
    const int brow = ((lane >> 4) & 1) * 8 + (lane & 7);
    const int bkg  = (lane >> 3) & 1;

    #pragma unroll
    for (int i = 0; i < WM * WN / 32; i++) acc[i] = 0.f;

    const int nch = K >> 5;

    auto load_chunk = [&](int i) {
        const int k0 = i << 5;
        const uint32_t st = smem_u32(sm + (i % 3) * STG);
        #pragma unroll
        for (int j = 0; j < BM / 64; j++) {
            int idx = tid + j * 256;
            int r = idx >> 2, kg = idx & 3;
            uint32_t o = swz(r, kg);
            cp16(st + o,      Ah + (size_t)r * lda + k0 + kg * 8);
            cp16(st + SA + o, Al + (size_t)r * lda + k0 + kg * 8);
        }
        #pragma unroll
        for (int j = 0; j < BN / 64; j++) {
            int idx = tid + j * 256;
            int r = idx >> 2, kg = idx & 3;
            uint32_t o = swz(r, kg);
            cp16(st + 2 * SA + o,      Bh + (size_t)r * ldb + k0 + kg * 8);
            cp16(st + 2 * SA + SB + o, Bl + (size_t)r * ldb + k0 + kg * 8);
        }
        CP_COMMIT();
    };

    load_chunk(0);
    if (nch > 1) load_chunk(1);

    for (int i = 0; i < nch; i++) {
        if (i + 1 < nch) { CP_WAIT(1); } else { CP_WAIT(0); }
        __syncthreads();
        if (i + 2 < nch) load_chunk(i + 2);

        const uint32_t st = smem_u32(sm + (i % 3) * STG);
        #pragma unroll
        for (int ks = 0; ks < 2; ks++) {
            uint32_t ah[WM / 16][4], al[WM / 16][4], bh[WN / 16][4], bl[WN / 16][4];
            #pragma unroll
            for (int im = 0; im < WM / 16; im++) {
                int row = wm * WM + im * 16 + arow;
                uint32_t o = swz(row, ks * 2 + akg);
                ldsm4(ah[im], st + o);
                ldsm4(al[im], st + SA + o);
            }
            #pragma unroll
            for (int j2 = 0; j2 < WN / 16; j2++) {
                int n = wn * WN + j2 * 16 + brow;
                uint32_t o = swz(n, ks * 2 + bkg);
                ldsm4(bh[j2], st + 2 * SA + o);
                ldsm4(bl[j2], st + 2 * SA + SB + o);
            }
            #pragma unroll
            for (int im = 0; im < WM / 16; im++)
                #pragma unroll
                for (int jn = 0; jn < WN / 8; jn++) {
                    float* c = acc + (im * (WN / 8) + jn) * 4;
                    const uint32_t* pbh = &bh[jn >> 1][(jn & 1) * 2];
                    const uint32_t* pbl = &bl[jn >> 1][(jn & 1) * 2];
                    mma16816(c, ah[im], pbh);
                    mma16816(c, ah[im], pbl);
                    mma16816(c, al[im], pbh);
                }
        }
    }
}

// epilogue iteration: f(row, col, val) over this thread's fragment elements
template<int BM, int BN, typename F>
__device__ __forceinline__ void epi(const float* acc, F&& f) {
    constexpr int WM = BM / 4, WN = BN / 2;
    const int lane = threadIdx.x & 31;
    const int warp = threadIdx.x >> 5;
    const int wm = warp >> 1, wn = warp & 1;
    const int g = lane >> 2, tg = lane & 3;
    #pragma unroll
    for (int im = 0; im < WM / 16; im++)
        #pragma unroll
        for (int jn = 0; jn < WN / 8; jn++)
            #pragma unroll
            for (int r = 0; r < 4; r++) {
                int row = wm * WM + im * 16 + g + ((r & 2) ? 8 : 0);
                int col = wn * WN + jn * 8 + tg * 2 + (r & 1);
                f(row, col, acc[(im * (WN / 8) + jn) * 4 + r]);
            }
}

#define SMEM_BIG   (3 * (2 * 128 * 64 + 2 * 128 * 64))   // 98304  (128x128 tiles)
#define SMEM_SMALL (3 * (2 * 128 * 64 + 2 * 64 * 64))    // 73728  (128x64 tiles)

// ---------------------------------------------------------------------------
// QKV projection: BM=128, BN=128 (z: 0=k scaled, 1=q scaled, 2=v -> Vt)
// ---------------------------------------------------------------------------
__global__ __launch_bounds__(256, 1) void proj_kernel() {
    const int n0 = blockIdx.x * 128;
    const int m0 = blockIdx.y * 128;
    const int z  = blockIdx.z;
    const bf16* Wh = (z == 0) ? g_wkh : (z == 1) ? g_wqh : g_wvh;
    const bf16* Wl = (z == 0) ? g_wkl : (z == 1) ? g_wql : g_wvl;

    float acc[64];
    tc_gemm<128, 128>(g_xh + (size_t)m0 * E, g_xl + (size_t)m0 * E, E,
                      Wh + (size_t)n0 * E,  Wl + (size_t)n0 * E,  E, E, acc);

    if (z == 2) {
        epi<128, 128>(acc, [&](int row, int col, float v) {
            int m = m0 + row, n = n0 + col;
            int b = m >> 10, t = m & 1023, h = n >> 9, ec = n & 511;
            size_t o = ((size_t)((b * H + h) * E + ec)) * T + t;
            f32split(v, g_vth[o], g_vtl[o]);
        });
    } else {
        bf16* Dh = (z == 0) ? g_kh : g_qh;
        bf16* Dl = (z == 0) ? g_kl : g_ql;
        epi<128, 128>(acc, [&](int row, int col, float v) {
            size_t o = (size_t)(m0 + row) * NPROJ + n0 + col;
            f32split(v * QK_SCALE, Dh[o], Dl[o]);
        });
    }
}

// ---------------------------------------------------------------------------
// Scores: BM=128 (q), BN=128 (k); only tiles touching the lower triangle
// ---------------------------------------------------------------------------
__global__ __launch_bounds__(256, 1) void scores_kernel() {
    const int k0 = blockIdx.x * 128;
    const int q0 = blockIdx.y * 128;
    if (k0 >= q0 + 128) return;
    const int bh = blockIdx.z;
    const int b = bh >> 3, h = bh & 7;
    const size_t base = (size_t)b * T * NPROJ + (size_t)h * E;

    float acc[64];
    tc_gemm<128, 128>(
        g_qh + base + (size_t)q0 * NPROJ, g_ql + base + (size_t)q0 * NPROJ, NPROJ,
        g_kh + base + (size_t)k0 * NPROJ, g_kl + base + (size_t)k0 * NPROJ, NPROJ,
        E, acc);

    float* S = g_s + (size_t)bh * T * T;
    epi<128, 128>(acc, [&](int row, int col, float v) {
        S[(size_t)(q0 + row) * T + k0 + col] = v;
    });
}

// ---------------------------------------------------------------------------
// Softmax row (valid keys [0, trow]); hi/lo probs, zeros above diagonal
// ---------------------------------------------------------------------------
__global__ void softmax_kernel() {
    const int row = blockIdx.x;
    const int trow = row & 1023;
    const float* __restrict__ S = g_s + (size_t)row * T;
    bf16* __restrict__ Ph = g_ph + (size_t)row * T;
    bf16* __restrict__ Pl = g_pl + (size_t)row * T;
    const int tid = threadIdx.x;
    __shared__ float red[256];

    float v[4];
    float m = NEG_INF;
    #pragma unroll
    for (int i = 0; i < 4; i++) {
        int idx = tid + i * 256;
        v[i] = (idx <= trow) ? S[idx] : NEG_INF;
        m = fmaxf(m, v[i]);
    }
    red[tid] = m; __syncthreads();
    for (int s = 128; s > 0; s >>= 1) {
        if (tid < s) red[tid] = fmaxf(red[tid], red[tid + s]);
        __syncthreads();
    }
    m = red[0]; __syncthreads();

    float sum = 0.f;
    #pragma unroll
    for (int i = 0; i < 4; i++) {
        int idx = tid + i * 256;
        v[i] = (idx <= trow) ? __expf(v[i] - m) : 0.f;
        sum += v[i];
    }
    red[tid] = sum; __syncthreads();
    for (int s = 128; s > 0; s >>= 1) {
        if (tid < s) red[tid] += red[tid + s];
        __syncthreads();
    }
    const float inv = 1.0f / red[0];
    #pragma unroll
    for (int i = 0; i < 4; i++) {
        int idx = tid + i * 256;
        f32split(v[i] * inv, Ph[idx], Pl[idx]);
    }
}

// ---------------------------------------------------------------------------
// AV: BM=128 (q), BN=128 (e); B operand = Vt, K = t truncated causally
// ---------------------------------------------------------------------------
__global__ __launch_bounds__(256, 1) void av_kernel() {
    const int n0 = blockIdx.x * 128;   // over E
    const int q0 = blockIdx.y * 128;
    const int bh = blockIdx.z;
    const int b = bh >> 3, h = bh & 7;
    const size_t pbase = (size_t)bh * T * T + (size_t)q0 * T;
    const size_t vbase = (size_t)bh * E * T + (size_t)n0 * T;

    float acc[64];
    tc_gemm<128, 128>(g_ph + pbase, g_pl + pbase, T,
                      g_vth + vbase, g_vtl + vbase, T,
                      q0 + 128, acc);

    epi<128, 128>(acc, [&](int row, int col, float v) {
        size_t o = (size_t)(b * T + q0 + row) * NPROJ + h * E + n0 + col;
        f32split(v, g_aoh[o], g_aol[o]);
    });
}

// ---------------------------------------------------------------------------
// Unify: BM=128, BN=64 (grid 8x32 keeps the chip filled); out = AO @ wu^T + bu
// ---------------------------------------------------------------------------
__global__ __launch_bounds__(256, 2) void unify_kernel(const float* __restrict__ bu,
                                                       float* __restrict__ out) {
    const int n0 = blockIdx.x * 64;    // over E
    const int m0 = blockIdx.y * 128;

    float acc[32];
    tc_gemm<128, 64>(g_aoh + (size_t)m0 * NPROJ, g_aol + (size_t)m0 * NPROJ, NPROJ,
                     g_wuh + (size_t)n0 * NPROJ, g_wul + (size_t)n0 * NPROJ, NPROJ,
                     NPROJ, acc);

    epi<128, 64>(acc, [&](int row, int col, float v) {
        out[(size_t)(m0 + row) * E + n0 + col] = v + bu[n0 + col];
    });
}

// ---------------------------------------------------------------------------
extern "C" void kernel_launch(void* const* d_in, const int* in_sizes, int n_in,
                              void* d_out, int out_size) {
    const float* x  = (const float*)d_in[0];
    const float* wk = (const float*)d_in[1];
    const float* wq = (const float*)d_in[2];
    const float* wv = (const float*)d_in[3];
    const float* wu = (const float*)d_in[4];
    const float* bu = (const float*)d_in[5];
    float* out = (float*)d_out;

    cudaFuncSetAttribute(proj_kernel,   cudaFuncAttributeMaxDynamicSharedMemorySize, SMEM_BIG);
    cudaFuncSetAttribute(scores_kernel, cudaFuncAttributeMaxDynamicSharedMemorySize, SMEM_BIG);
    cudaFuncSetAttribute(av_kernel,     cudaFuncAttributeMaxDynamicSharedMemorySize, SMEM_BIG);
    cudaFuncSetAttribute(unify_kernel,  cudaFuncAttributeMaxDynamicSharedMemorySize, SMEM_SMALL);

    split_all<<<dim3(MTOT * E / 256, 5), 256>>>(x, wk, wq, wv, wu);

    proj_kernel  <<<dim3(NPROJ / 128, MTOT / 128, 3), 256, SMEM_BIG>>>();
    scores_kernel<<<dim3(T / 128, T / 128, BH),        256, SMEM_BIG>>>();
    softmax_kernel<<<BH * T, 256>>>();
    av_kernel    <<<dim3(E / 128, T / 128, BH),        256, SMEM_BIG>>>();
    unify_kernel <<<dim3(E / 64, MTOT / 128),          256, SMEM_SMALL>>>(bu, out);
}

// round 7
// speedup vs baseline: 1.2183x; 1.2183x over previous
#include <cuda_runtime.h>
#include <cuda_bf16.h>
#include <cstdint>

// Problem shape (fixed)
#define Bb    4
#define T     1024
#define E     512
#define H     8
#define MTOT  (Bb*T)       // 4096
#define NPROJ (H*E)        // 4096
#define BH    (Bb*H)       // 32

#define NEG_INF (__int_as_float(0xff800000))
#define QK_SCALE 0.21022410381342864f   // 512^-0.25

typedef __nv_bfloat16 bf16;

// ---------------- scratch (device globals; no allocs allowed) ----------------
__device__ __align__(16) bf16 g_xh[MTOT * E],   g_xl[MTOT * E];
__device__ __align__(16) bf16 g_wkh[NPROJ * E], g_wkl[NPROJ * E];
__device__ __align__(16) bf16 g_wqh[NPROJ * E], g_wql[NPROJ * E];
__device__ __align__(16) bf16 g_wvh[NPROJ * E], g_wvl[NPROJ * E];
__device__ __align__(16) bf16 g_wuh[E * NPROJ], g_wul[E * NPROJ];
__device__ __align__(16) bf16 g_qh[MTOT * NPROJ], g_ql[MTOT * NPROJ];  // pre-scaled
__device__ __align__(16) bf16 g_kh[MTOT * NPROJ], g_kl[MTOT * NPROJ];  // pre-scaled
__device__ __align__(16) bf16 g_vth[(size_t)BH * E * T], g_vtl[(size_t)BH * E * T]; // (b,h,e,t)
__device__ float g_s[(size_t)BH * T * T];
__device__ __align__(16) bf16 g_ph[(size_t)BH * T * T], g_pl[(size_t)BH * T * T];
__device__ __align__(16) bf16 g_aoh[MTOT * NPROJ], g_aol[MTOT * NPROJ];

// ---------------------------------------------------------------------------
__device__ __forceinline__ uint32_t smem_u32(const void* p) {
    uint32_t a;
    asm("{ .reg .u64 t; cvta.to.shared.u64 t, %1; cvt.u32.u64 %0, t; }" : "=r"(a) : "l"(p));
    return a;
}
__device__ __forceinline__ void cp16(uint32_t dst, const void* src) {
    asm volatile("cp.async.cg.shared.global [%0], [%1], 16;" :: "r"(dst), "l"(src) : "memory");
}
#define CP_COMMIT()  asm volatile("cp.async.commit_group;" ::: "memory")
#define CP_WAIT(n)   asm volatile("cp.async.wait_group %0;" :: "n"(n) : "memory")

__device__ __forceinline__ void ldsm4(uint32_t* r, uint32_t addr) {
    asm volatile("ldmatrix.sync.aligned.m8n8.x4.shared.b16 {%0,%1,%2,%3}, [%4];"
                 : "=r"(r[0]), "=r"(r[1]), "=r"(r[2]), "=r"(r[3]) : "r"(addr));
}
__device__ __forceinline__ void mma16816(float* c, const uint32_t* a, const uint32_t* b) {
    asm volatile(
        "mma.sync.aligned.m16n8k16.row.col.f32.bf16.bf16.f32 "
        "{%0,%1,%2,%3}, {%4,%5,%6,%7}, {%8,%9}, {%0,%1,%2,%3};"
        : "+f"(c[0]), "+f"(c[1]), "+f"(c[2]), "+f"(c[3])
        : "r"(a[0]), "r"(a[1]), "r"(a[2]), "r"(a[3]), "r"(b[0]), "r"(b[1]));
}

__device__ __forceinline__ void f32split(float x, bf16& h, bf16& l) {
    h = __float2bfloat16(x);
    l = __float2bfloat16(x - __bfloat162float(h));
}

// all 5 arrays are exactly MTOT*E = 2M elements: one merged launch
__global__ void split_all(const float* __restrict__ x,  const float* __restrict__ wk,
                          const float* __restrict__ wq, const float* __restrict__ wv,
                          const float* __restrict__ wu) {
    const int i = blockIdx.x * 256 + threadIdx.x;
    const float* s; bf16 *h, *l;
    switch (blockIdx.y) {
        case 0:  s = x;  h = g_xh;  l = g_xl;  break;
        case 1:  s = wk; h = g_wkh; l = g_wkl; break;
        case 2:  s = wq; h = g_wqh; l = g_wql; break;
        case 3:  s = wv; h = g_wvh; l = g_wvl; break;
        default: s = wu; h = g_wuh; l = g_wul; break;
    }
    f32split(s[i], h[i], l[i]);
}

// SW128-style swizzle: 128B rows (64 bf16 of K per row), kg = 16B group 0..7
__device__ __forceinline__ uint32_t swz(int row, int kg) {
    return row * 128 + ((kg ^ (row & 7)) << 4);
}

// ---------------------------------------------------------------------------
// GEMM core: C[BM,BN] = Ahi/lo[BM,K] x Bhi/lo[BN,K]^T (K-major, bf16x3)
// 256 threads, warp grid 4(m) x 2(n), warp tile BM/4 x BN/2 (= 32x32).
// K-chunk 64, 2-stage cp.async, ONE __syncthreads per chunk:
//   wait(chunk i) ; sync ; prefetch(chunk i+1) ; compute(chunk i)
// The sync both publishes chunk i to all warps and certifies buffer (i+1)&1
// (read at iter i-1) is free for the prefetch.
// ---------------------------------------------------------------------------
template<int BM, int BN>
__device__ __forceinline__ void tc_gemm(
    const bf16* __restrict__ Ah, const bf16* __restrict__ Al, int lda,
    const bf16* __restrict__ Bh, const bf16* __restrict__ Bl, int ldb,
    int K, float* acc)
{
    constexpr int WM = BM / 4, WN = BN / 2;
    constexpr int SA = BM * 128;         // bytes of one A array per stage
    constexpr int SB = BN * 128;
    constexpr int STG = 2 * SA + 2 * SB; // stage bytes
    extern __shared__ char sm[];

    const int tid  = threadIdx.x;
    const int lane = tid & 31;
    const int warp = tid >> 5;
    const int wm = warp >> 1, wn = warp & 1;

    // ldmatrix lane->element mapping
    const int arow = ((lane >> 3) & 1) * 8 + (lane & 7);
    const int akg  = (lane >> 4) & 1;
    const int brow = ((lane >> 4) & 1) * 8 + (lane & 7);
    const int bkg  = (lane >> 3) & 1;

    #pragma unroll
    for (int i = 0; i < WM * WN / 32; i++) acc[i] = 0.f;

    const int nch = K >> 6;

    auto load_chunk = [&](int i) {
        const int k0 = i << 6;
        const uint32_t st = smem_u32(sm + (i & 1) * STG);
        #pragma unroll
        for (int j = 0; j < BM / 32; j++) {          // BM*8 16B-chunks / 256 thr
            int idx = tid + j * 256;
            int r = idx >> 3, kg = idx & 7;
            uint32_t o = swz(r, kg);
            cp16(st + o,      Ah + (size_t)r * lda + k0 + kg * 8);
            cp16(st + SA + o, Al + (size_t)r * lda + k0 + kg * 8);
        }
        #pragma unroll
        for (int j = 0; j < BN / 32; j++) {
            int idx = tid + j * 256;
            int r = idx >> 3, kg = idx & 7;
            uint32_t o = swz(r, kg);
            cp16(st + 2 * SA + o,      Bh + (size_t)r * ldb + k0 + kg * 8);
            cp16(st + 2 * SA + SB + o, Bl + (size_t)r * ldb + k0 + kg * 8);
        }
        CP_COMMIT();
    };

    load_chunk(0);

    for (int i = 0; i < nch; i++) {
        CP_WAIT(0);            // chunk i resident (prefetched during iter i-1)
        __syncthreads();
        if (i + 1 < nch) load_chunk(i + 1);   // overlaps compute below

        const uint32_t st = smem_u32(sm + (i & 1) * STG);
        #pragma unroll
        for (int ks = 0; ks < 4; ks++) {
            uint32_t ah[WM / 16][4], al[WM / 16][4], bh[WN / 16][4], bl[WN / 16][4];
            #pragma unroll
            for (int im = 0; im < WM / 16; im++) {
                int row = wm * WM + im * 16 + arow;
                uint32_t o = swz(row, ks * 2 + akg);
                ldsm4(ah[im], st + o);
                ldsm4(al[im], st + SA + o);
            }
            #pragma unroll
            for (int j2 = 0; j2 < WN / 16; j2++) {
                int n = wn * WN + j2 * 16 + brow;
                uint32_t o = swz(n, ks * 2 + bkg);
                ldsm4(bh[j2], st + 2 * SA + o);
                ldsm4(bl[j2], st + 2 * SA + SB + o);
            }
            #pragma unroll
            for (int im = 0; im < WM / 16; im++)
                #pragma unroll
                for (int jn = 0; jn < WN / 8; jn++) {
                    float* c = acc + (im * (WN / 8) + jn) * 4;
                    const uint32_t* pbh = &bh[jn >> 1][(jn & 1) * 2];
                    const uint32_t* pbl = &bl[jn >> 1][(jn & 1) * 2];
                    mma16816(c, ah[im], pbh);
                    mma16816(c, ah[im], pbl);
                    mma16816(c, al[im], pbh);
                }
        }
    }
}

// epilogue iteration: f(row, col, val) over this thread's fragment elements
template<int BM, int BN, typename F>
__device__ __forceinline__ void epi(const float* acc, F&& f) {
    constexpr int WM = BM / 4, WN = BN / 2;
    const int lane = threadIdx.x & 31;
    const int warp = threadIdx.x >> 5;
    const int wm = warp >> 1, wn = warp & 1;
    const int g = lane >> 2, tg = lane & 3;
    #pragma unroll
    for (int im = 0; im < WM / 16; im++)
        #pragma unroll
        for (int jn = 0; jn < WN / 8; jn++)
            #pragma unroll
            for (int r = 0; r < 4; r++) {
                int row = wm * WM + im * 16 + g + ((r & 2) ? 8 : 0);
                int col = wn * WN + jn * 8 + tg * 2 + (r & 1);
                f(row, col, acc[(im * (WN / 8) + jn) * 4 + r]);
            }
}

// stage = 2*(128*128) + 2*(64*128) = 48 KB; 2 stages = 96 KB
#define SMEM_GEMM (2 * (2 * 128 * 128 + 2 * 64 * 128))

// ---------------------------------------------------------------------------
// QKV projection: BM=128, BN=64 (z: 0=k scaled, 1=q scaled, 2=v -> Vt)
// ---------------------------------------------------------------------------
__global__ __launch_bounds__(256, 2) void proj_kernel() {
    const int n0 = blockIdx.x * 64;
    const int m0 = blockIdx.y * 128;
    const int z  = blockIdx.z;
    const bf16* Wh = (z == 0) ? g_wkh : (z == 1) ? g_wqh : g_wvh;
    const bf16* Wl = (z == 0) ? g_wkl : (z == 1) ? g_wql : g_wvl;

    float acc[32];
    tc_gemm<128, 64>(g_xh + (size_t)m0 * E, g_xl + (size_t)m0 * E, E,
                     Wh + (size_t)n0 * E,  Wl + (size_t)n0 * E,  E, E, acc);

    if (z == 2) {
        epi<128, 64>(acc, [&](int row, int col, float v) {
            int m = m0 + row, n = n0 + col;
            int b = m >> 10, t = m & 1023, h = n >> 9, ec = n & 511;
            size_t o = ((size_t)((b * H + h) * E + ec)) * T + t;
            f32split(v, g_vth[o], g_vtl[o]);
        });
    } else {
        bf16* Dh = (z == 0) ? g_kh : g_qh;
        bf16* Dl = (z == 0) ? g_kl : g_ql;
        epi<128, 64>(acc, [&](int row, int col, float v) {
            size_t o = (size_t)(m0 + row) * NPROJ + n0 + col;
            f32split(v * QK_SCALE, Dh[o], Dl[o]);
        });
    }
}

// ---------------------------------------------------------------------------
// Scores: BM=128 (q), BN=64 (k); only tiles touching the lower triangle
// ---------------------------------------------------------------------------
__global__ __launch_bounds__(256, 2) void scores_kernel() {
    const int k0 = blockIdx.x * 64;
    const int q0 = blockIdx.y * 128;
    if (k0 >= q0 + 128) return;
    const int bh = blockIdx.z;
    const int b = bh >> 3, h = bh & 7;
    const size_t base = (size_t)b * T * NPROJ + (size_t)h * E;

    float acc[32];
    tc_gemm<128, 64>(
        g_qh + base + (size_t)q0 * NPROJ, g_ql + base + (size_t)q0 * NPROJ, NPROJ,
        g_kh + base + (size_t)k0 * NPROJ, g_kl + base + (size_t)k0 * NPROJ, NPROJ,
        E, acc);

    float* S = g_s + (size_t)bh * T * T;
    epi<128, 64>(acc, [&](int row, int col, float v) {
        S[(size_t)(q0 + row) * T + k0 + col] = v;
    });
}

// ---------------------------------------------------------------------------
// Softmax row (valid keys [0, trow]); hi/lo probs.  Writes only
// k < roundup128(trow+1) — av never reads past the diagonal 128-tile.
// ---------------------------------------------------------------------------
__global__ void softmax_kernel() {
    const int row = blockIdx.x;
    const int trow = row & 1023;
    const int kend = (trow & ~127) + 128;      // write bound
    const float* __restrict__ S = g_s + (size_t)row * T;
    bf16* __restrict__ Ph = g_ph + (size_t)row * T;
    bf16* __restrict__ Pl = g_pl + (size_t)row * T;
    const int tid = threadIdx.x;
    __shared__ float red[256];

    float v[4];
    float m = NEG_INF;
    #pragma unroll
    for (int i = 0; i < 4; i++) {
        int idx = tid + i * 256;
        v[i] = (idx <= trow) ? S[idx] : NEG_INF;
        m = fmaxf(m, v[i]);
    }
    red[tid] = m; __syncthreads();
    for (int s = 128; s > 0; s >>= 1) {
        if (tid < s) red[tid] = fmaxf(red[tid], red[tid + s]);
        __syncthreads();
    }
    m = red[0]; __syncthreads();

    float sum = 0.f;
    #pragma unroll
    for (int i = 0; i < 4; i++) {
        int idx = tid + i * 256;
        v[i] = (idx <= trow) ? __expf(v[i] - m) : 0.f;
        sum += v[i];
    }
    red[tid] = sum; __syncthreads();
    for (int s = 128; s > 0; s >>= 1) {
        if (tid < s) red[tid] += red[tid + s];
        __syncthreads();
    }
    const float inv = 1.0f / red[0];
    #pragma unroll
    for (int i = 0; i < 4; i++) {
        int idx = tid + i * 256;
        if (idx < kend) f32split(v[i] * inv, Ph[idx], Pl[idx]);
    }
}

// ---------------------------------------------------------------------------
// AV: BM=128 (q), BN=64 (e); B operand = Vt, K = t truncated causally
// ---------------------------------------------------------------------------
__global__ __launch_bounds__(256, 2) void av_kernel() {
    const int n0 = blockIdx.x * 64;    // over E
    const int q0 = blockIdx.y * 128;
    const int bh = blockIdx.z;
    const int b = bh >> 3, h = bh & 7;
    const size_t pbase = (size_t)bh * T * T + (size_t)q0 * T;
    const size_t vbase = (size_t)bh * E * T + (size_t)n0 * T;

    float acc[32];
    tc_gemm<128, 64>(g_ph + pbase, g_pl + pbase, T,
                     g_vth + vbase, g_vtl + vbase, T,
                     q0 + 128, acc);

    epi<128, 64>(acc, [&](int row, int col, float v) {
        size_t o = (size_t)(b * T + q0 + row) * NPROJ + h * E + n0 + col;
        f32split(v, g_aoh[o], g_aol[o]);
    });
}

// ---------------------------------------------------------------------------
// Unify: BM=128, BN=64; out = AO @ wu^T + bu
// ---------------------------------------------------------------------------
__global__ __launch_bounds__(256, 2) void unify_kernel(const float* __restrict__ bu,
                                                       float* __restrict__ out) {
    const int n0 = blockIdx.x * 64;    // over E
    const int m0 = blockIdx.y * 128;

    float acc[32];
    tc_gemm<128, 64>(g_aoh + (size_t)m0 * NPROJ, g_aol + (size_t)m0 * NPROJ, NPROJ,
                     g_wuh + (size_t)n0 * NPROJ, g_wul + (size_t)n0 * NPROJ, NPROJ,
                     NPROJ, acc);

    epi<128, 64>(acc, [&](int row, int col, float v) {
        out[(size_t)(m0 + row) * E + n0 + col] = v + bu[n0 + col];
    });
}

// ---------------------------------------------------------------------------
extern "C" void kernel_launch(void* const* d_in, const int* in_sizes, int n_in,
                              void* d_out, int out_size) {
    const float* x  = (const float*)d_in[0];
    const float* wk = (const float*)d_in[1];
    const float* wq = (const float*)d_in[2];
    const float* wv = (const float*)d_in[3];
    const float* wu = (const float*)d_in[4];
    const float* bu = (const float*)d_in[5];
    float* out = (float*)d_out;

    cudaFuncSetAttribute(proj_kernel,   cudaFuncAttributeMaxDynamicSharedMemorySize, SMEM_GEMM);
    cudaFuncSetAttribute(scores_kernel, cudaFuncAttributeMaxDynamicSharedMemorySize, SMEM_GEMM);
    cudaFuncSetAttribute(av_kernel,     cudaFuncAttributeMaxDynamicSharedMemorySize, SMEM_GEMM);
    cudaFuncSetAttribute(unify_kernel,  cudaFuncAttributeMaxDynamicSharedMemorySize, SMEM_GEMM);

    split_all<<<dim3(MTOT * E / 256, 5), 256>>>(x, wk, wq, wv, wu);

    proj_kernel  <<<dim3(NPROJ / 64, MTOT / 128, 3), 256, SMEM_GEMM>>>();
    scores_kernel<<<dim3(T / 64, T / 128, BH),        256, SMEM_GEMM>>>();
    softmax_kernel<<<BH * T, 256>>>();
    av_kernel    <<<dim3(E / 64, T / 128, BH),        256, SMEM_GEMM>>>();
    unify_kernel <<<dim3(E / 64, MTOT / 128),         256, SMEM_GEMM>>>(bu, out);
}